// round 1
// baseline (speedup 1.0000x reference)
#include <cuda_runtime.h>

// BahdanauScorer: scores[b,s] = sum_a v_a[a] * tanh( dot(enc[s,b,:], W_s[a,:])
//                                                  + dot(dec[b,:],  W_t[a,:]) + b_t[a] )
// Shapes: enc (2048,64,512) f32; dec (64,512); W_s,W_t (512,512); b_t,v_a (512)
// Output: (64, 2048) f32.

#define S_LEN  2048
#define BATCH  64
#define HID    512
#define ATT    512
#define TS     32        // s-rows per block
#define NTHR   256
#define F4ROW  (HID / 4) // 128 float4 per row

// scratch for dec_att (64 x 512 f32) -- device global, no allocations
__device__ float g_dec_att[BATCH * ATT];

__device__ __forceinline__ float tanh_fast(float x) {
    float y;
    asm("tanh.approx.f32 %0, %1;" : "=f"(y) : "f"(x));
    return y;
}

// ---------------- stage 1: dec_att[b,a] = dec[b] . W_t[a] + b_t[a] ----------------
__global__ void dec_att_kernel(const float* __restrict__ dec_out,
                               const float* __restrict__ W_t,
                               const float* __restrict__ b_t) {
    int b = blockIdx.x;
    __shared__ float dsh[HID];
    for (int i = threadIdx.x; i < HID; i += blockDim.x)
        dsh[i] = dec_out[b * HID + i];
    __syncthreads();

    const float4* dsh4 = reinterpret_cast<const float4*>(dsh);
    for (int a = threadIdx.x; a < ATT; a += blockDim.x) {
        const float4* w4 = reinterpret_cast<const float4*>(W_t + (size_t)a * HID);
        float acc = 0.f;
#pragma unroll 8
        for (int h4 = 0; h4 < F4ROW; ++h4) {
            float4 w = __ldg(&w4[h4]);
            float4 d = dsh4[h4];
            acc += w.x * d.x + w.y * d.y + w.z * d.z + w.w * d.w;
        }
        g_dec_att[b * ATT + a] = acc + b_t[a];
    }
}

// ---------------- stage 2: main scorer ----------------
// grid: (S_LEN/TS, BATCH). block: 256 threads. dynamic smem: TS*HID floats (64KB).
extern "C" __global__ void __launch_bounds__(NTHR, 2)
score_kernel(const float* __restrict__ enc,
             const float* __restrict__ W_s,
             const float* __restrict__ v_a,
             float* __restrict__ out) {
    extern __shared__ float smem[];           // enc tile, later reused for reduction
    float4* esh = reinterpret_cast<float4*>(smem);

    const int b  = blockIdx.y;
    const int s0 = blockIdx.x * TS;

    // cooperative, coalesced load of the 32x512 enc tile
    for (int idx = threadIdx.x; idx < TS * F4ROW; idx += NTHR) {
        int r = idx >> 7;          // idx / 128
        int c = idx & 127;         // idx % 128
        const float4* src =
            reinterpret_cast<const float4*>(enc + ((size_t)(s0 + r) * BATCH + b) * HID);
        esh[r * F4ROW + c] = __ldg(src + c);
    }
    __syncthreads();

    const int a0 = threadIdx.x;          // 0..255
    const int a1 = threadIdx.x + NTHR;   // 256..511
    const float4* w0p = reinterpret_cast<const float4*>(W_s + (size_t)a0 * HID);
    const float4* w1p = reinterpret_cast<const float4*>(W_s + (size_t)a1 * HID);

    float acc0[TS], acc1[TS];
#pragma unroll
    for (int r = 0; r < TS; ++r) { acc0[r] = 0.f; acc1[r] = 0.f; }

    // main loop: per h4 step: 2 LDG.128 (W, L1/L2-resident) + 32 LDS.128 + 256 FMA
    for (int h4 = 0; h4 < F4ROW; ++h4) {
        float4 w0 = __ldg(w0p + h4);
        float4 w1 = __ldg(w1p + h4);
#pragma unroll
        for (int r = 0; r < TS; ++r) {
            float4 e = esh[r * F4ROW + h4];   // warp-uniform address -> broadcast
            acc0[r] += w0.x * e.x + w0.y * e.y + w0.z * e.z + w0.w * e.w;
            acc1[r] += w1.x * e.x + w1.y * e.y + w1.z * e.z + w1.w * e.w;
        }
    }

    const float d0 = g_dec_att[b * ATT + a0];
    const float d1 = g_dec_att[b * ATT + a1];
    const float v0 = __ldg(v_a + a0);
    const float v1 = __ldg(v_a + a1);

    float part[TS];
#pragma unroll
    for (int r = 0; r < TS; ++r)
        part[r] = v0 * tanh_fast(acc0[r] + d0) + v1 * tanh_fast(acc1[r] + d1);

    // reduce over the 256 threads (a-dimension) for each of the TS rows
    const int lane = threadIdx.x & 31;
    const int wid  = threadIdx.x >> 5;
#pragma unroll
    for (int r = 0; r < TS; ++r) {
        float p = part[r];
        p += __shfl_xor_sync(0xffffffffu, p, 16);
        p += __shfl_xor_sync(0xffffffffu, p, 8);
        p += __shfl_xor_sync(0xffffffffu, p, 4);
        p += __shfl_xor_sync(0xffffffffu, p, 2);
        p += __shfl_xor_sync(0xffffffffu, p, 1);
        part[r] = p;                     // lane 0 holds the warp sum
    }

    __syncthreads();                     // done reading esh; reuse smem
    float* red = smem;                   // [8 warps][TS]
    if (lane == 0) {
#pragma unroll
        for (int r = 0; r < TS; ++r) red[wid * TS + r] = part[r];
    }
    __syncthreads();

    if (threadIdx.x < TS) {
        int r = threadIdx.x;
        float s = 0.f;
#pragma unroll
        for (int w = 0; w < 8; ++w) s += red[w * TS + r];
        out[(size_t)b * S_LEN + s0 + r] = s;
    }
}

// ---------------- launch ----------------
extern "C" void kernel_launch(void* const* d_in, const int* in_sizes, int n_in,
                              void* d_out, int out_size) {
    const float* dec_out = (const float*)d_in[0];   // (64, 512)
    const float* enc     = (const float*)d_in[1];   // (2048, 64, 512)
    const float* W_s     = (const float*)d_in[2];   // (512, 512)
    const float* W_t     = (const float*)d_in[3];   // (512, 512)
    const float* b_t     = (const float*)d_in[4];   // (512,)
    const float* v_a     = (const float*)d_in[5];   // (512,)
    float* out = (float*)d_out;                     // (64, 2048)

    (void)in_sizes; (void)n_in; (void)out_size;

    const int smem_bytes = TS * HID * sizeof(float); // 64 KB
    cudaFuncSetAttribute(score_kernel,
                         cudaFuncAttributeMaxDynamicSharedMemorySize, smem_bytes);

    dec_att_kernel<<<BATCH, 256>>>(dec_out, W_t, b_t);

    dim3 grid(S_LEN / TS, BATCH);
    score_kernel<<<grid, NTHR, smem_bytes>>>(enc, W_s, v_a, out);
}

// round 3
// speedup vs baseline: 2.8833x; 2.8833x over previous
#include <cuda_runtime.h>
#include <cuda_bf16.h>
#include <cstdint>

// BahdanauScorer: scores[b,s] = sum_a v_a[a] * tanh( enc[s,b,:].W_s[a,:] + dec[b,:].W_t[a,:] + b_t[a] )
// enc (2048,64,512) f32; dec (64,512); W_s,W_t (512,512); b_t,v_a (512); out (64,2048) f32.
//
// mma.sync (HMMA) bf16 split-3 GEMM: e*w ~= e_hi*w_hi + e_lo*w_hi + e_hi*w_lo.

#define S_LEN  2048
#define BATCH  64
#define HID    512
#define ATT    512
#define MT     128
#define AC_N   128      // a per chunk
#define KC     64       // k per chunk
#define NTHR   512

// device scratch
__device__ float         g_dec_att[BATCH * ATT];
__device__ __nv_bfloat16 g_W_hi[ATT * HID];
__device__ __nv_bfloat16 g_W_lo[ATT * HID];

// smem offsets (bytes): 4 tiles of 128x64 bf16 (16KB each), then dec/v/score
#define SM_A_HI  0
#define SM_A_LO  16384
#define SM_B_HI  32768
#define SM_B_LO  49152
#define SM_DEC   65536
#define SM_V     67584
#define SM_SCORE 69632
#define SM_TOTAL 70656

__device__ __forceinline__ uint32_t smem_u32(const void* p) {
    uint32_t a;
    asm("{ .reg .u64 t; cvta.to.shared.u64 t, %1; cvt.u32.u64 %0, t; }" : "=r"(a) : "l"(p));
    return a;
}
__device__ __forceinline__ void ldsm4(uint32_t addr, uint32_t* r) {
    asm volatile("ldmatrix.sync.aligned.m8n8.x4.shared.b16 {%0,%1,%2,%3}, [%4];"
                 : "=r"(r[0]), "=r"(r[1]), "=r"(r[2]), "=r"(r[3]) : "r"(addr));
}
#define MMA(d, a, b0, b1)                                                        \
    asm volatile("mma.sync.aligned.m16n8k16.row.col.f32.bf16.bf16.f32 "          \
                 "{%0,%1,%2,%3},{%4,%5,%6,%7},{%8,%9},{%0,%1,%2,%3};"            \
                 : "+f"((d)[0]), "+f"((d)[1]), "+f"((d)[2]), "+f"((d)[3])        \
                 : "r"((a)[0]), "r"((a)[1]), "r"((a)[2]), "r"((a)[3]),           \
                   "r"(b0), "r"(b1))

__device__ __forceinline__ float tanh_fast(float x) {
    float y;
    asm("tanh.approx.f32 %0, %1;" : "=f"(y) : "f"(x));
    return y;
}
__device__ __forceinline__ uint32_t split2(float x0, float x1, uint32_t& lo) {
    __nv_bfloat16 h0 = __float2bfloat16(x0), h1 = __float2bfloat16(x1);
    __nv_bfloat16 l0 = __float2bfloat16(x0 - __bfloat162float(h0));
    __nv_bfloat16 l1 = __float2bfloat16(x1 - __bfloat162float(h1));
    lo = (uint32_t)__bfloat16_as_ushort(l0) | ((uint32_t)__bfloat16_as_ushort(l1) << 16);
    return (uint32_t)__bfloat16_as_ushort(h0) | ((uint32_t)__bfloat16_as_ushort(h1) << 16);
}

// ---------------- prep kernels ----------------
__global__ void w_prep_kernel(const float* __restrict__ W_s) {
    int i = blockIdx.x * blockDim.x + threadIdx.x;
    float x = W_s[i];
    __nv_bfloat16 h = __float2bfloat16(x);
    g_W_hi[i] = h;
    g_W_lo[i] = __float2bfloat16(x - __bfloat162float(h));
}

__global__ void dec_att_kernel(const float* __restrict__ dec_out,
                               const float* __restrict__ W_t,
                               const float* __restrict__ b_t) {
    int b = blockIdx.x;
    __shared__ float dsh[HID];
    for (int i = threadIdx.x; i < HID; i += blockDim.x)
        dsh[i] = dec_out[b * HID + i];
    __syncthreads();
    const float4* dsh4 = reinterpret_cast<const float4*>(dsh);
    for (int a = threadIdx.x; a < ATT; a += blockDim.x) {
        const float4* w4 = reinterpret_cast<const float4*>(W_t + (size_t)a * HID);
        float acc = 0.f;
#pragma unroll 8
        for (int h4 = 0; h4 < HID / 4; ++h4) {
            float4 w = __ldg(&w4[h4]);
            float4 d = dsh4[h4];
            acc += w.x * d.x + w.y * d.y + w.z * d.z + w.w * d.w;
        }
        g_dec_att[b * ATT + a] = acc + b_t[a];
    }
}

// ---------------- main kernel ----------------
extern "C" __global__ void __launch_bounds__(NTHR, 1)
score_mma_kernel(const float* __restrict__ enc,
                 const float* __restrict__ v_a,
                 float* __restrict__ out) {
    extern __shared__ char smem[];
    const uint32_t sb = smem_u32(smem);
    const int tid = threadIdx.x;
    const int lane = tid & 31, wid = tid >> 5;
    const int g = lane >> 2, c = lane & 3, l7 = lane & 7;
    const int t8 = (lane >> 3) & 1, t16 = lane >> 4;
    const int wm = wid & 3, wn = wid >> 2;
    const int mbase = wm * 32, nbase = wn * 32;
    const int b = blockIdx.y, s0 = blockIdx.x * MT;

    // init dec/v/score smem
    float* dec_s = reinterpret_cast<float*>(smem + SM_DEC);
    float* v_s   = reinterpret_cast<float*>(smem + SM_V);
    float* score = reinterpret_cast<float*>(smem + SM_SCORE);
    if (tid < 512) {
        dec_s[tid] = g_dec_att[b * ATT + tid];
        v_s[tid]   = __ldg(v_a + tid);
    }
    if (tid < MT) score[tid] = 0.f;

    // ldmatrix row bases (constant across chunks)
    const int arow = mbase + t8 * 8 + l7;     // +16 for mi=1
    const int brow = nbase + t16 * 8 + l7;    // +16 for nj2=1
    const int axor = arow & 7;                // (row+16)&7 == row&7
    const int bxor = brow & 7;

    // staged gmem data for one chunk
    float4 Araw[4];
    uint4  Bh[2], Bl[2];

    const int q0 = tid, q1 = tid + NTHR;      // two 16B chunks per thread per tile
    const int ar0 = q0 >> 3, ak0 = q0 & 7;
    const int ar1 = q1 >> 3, ak1 = q1 & 7;

    // prologue: stage chunk (ac=0, kc=0)
    {
        const float4* p0 = reinterpret_cast<const float4*>(
            enc + ((size_t)(s0 + ar0) * BATCH + b) * HID + ak0 * 8);
        const float4* p1 = reinterpret_cast<const float4*>(
            enc + ((size_t)(s0 + ar1) * BATCH + b) * HID + ak1 * 8);
        Araw[0] = __ldg(p0); Araw[1] = __ldg(p0 + 1);
        Araw[2] = __ldg(p1); Araw[3] = __ldg(p1 + 1);
        size_t g0 = (size_t)ar0 * HID + ak0 * 8;
        size_t g1 = (size_t)ar1 * HID + ak1 * 8;
        Bh[0] = __ldg(reinterpret_cast<const uint4*>(g_W_hi + g0));
        Bh[1] = __ldg(reinterpret_cast<const uint4*>(g_W_hi + g1));
        Bl[0] = __ldg(reinterpret_cast<const uint4*>(g_W_lo + g0));
        Bl[1] = __ldg(reinterpret_cast<const uint4*>(g_W_lo + g1));
    }

    for (int it = 0; it < 32; ++it) {         // it = ac*8 + kc
        __syncthreads();                      // previous mma phase done, tiles free

        // ---- STS phase: convert + store staged regs ----
        {
            uint32_t sw0 = (uint32_t)(ar0 * 128 + ((ak0 ^ (ar0 & 7)) << 4));
            uint32_t sw1 = (uint32_t)(ar1 * 128 + ((ak1 ^ (ar1 & 7)) << 4));
            uint4 h, l;
            h.x = split2(Araw[0].x, Araw[0].y, l.x);
            h.y = split2(Araw[0].z, Araw[0].w, l.y);
            h.z = split2(Araw[1].x, Araw[1].y, l.z);
            h.w = split2(Araw[1].z, Araw[1].w, l.w);
            *reinterpret_cast<uint4*>(smem + SM_A_HI + sw0) = h;
            *reinterpret_cast<uint4*>(smem + SM_A_LO + sw0) = l;
            h.x = split2(Araw[2].x, Araw[2].y, l.x);
            h.y = split2(Araw[2].z, Araw[2].w, l.y);
            h.z = split2(Araw[3].x, Araw[3].y, l.z);
            h.w = split2(Araw[3].z, Araw[3].w, l.w);
            *reinterpret_cast<uint4*>(smem + SM_A_HI + sw1) = h;
            *reinterpret_cast<uint4*>(smem + SM_A_LO + sw1) = l;
            *reinterpret_cast<uint4*>(smem + SM_B_HI + sw0) = Bh[0];
            *reinterpret_cast<uint4*>(smem + SM_B_HI + sw1) = Bh[1];
            *reinterpret_cast<uint4*>(smem + SM_B_LO + sw0) = Bl[0];
            *reinterpret_cast<uint4*>(smem + SM_B_LO + sw1) = Bl[1];
        }
        __syncthreads();

        // ---- stage next chunk's gmem loads (hide latency under mma) ----
        if (it + 1 < 32) {
            const int nac = (it + 1) >> 3, nkc = (it + 1) & 7;
            const int k0 = nkc * KC, a0 = nac * AC_N;
            const float4* p0 = reinterpret_cast<const float4*>(
                enc + ((size_t)(s0 + ar0) * BATCH + b) * HID + k0 + ak0 * 8);
            const float4* p1 = reinterpret_cast<const float4*>(
                enc + ((size_t)(s0 + ar1) * BATCH + b) * HID + k0 + ak1 * 8);
            Araw[0] = __ldg(p0); Araw[1] = __ldg(p0 + 1);
            Araw[2] = __ldg(p1); Araw[3] = __ldg(p1 + 1);
            size_t g0 = (size_t)(a0 + ar0) * HID + k0 + ak0 * 8;
            size_t g1 = (size_t)(a0 + ar1) * HID + k0 + ak1 * 8;
            Bh[0] = __ldg(reinterpret_cast<const uint4*>(g_W_hi + g0));
            Bh[1] = __ldg(reinterpret_cast<const uint4*>(g_W_hi + g1));
            Bl[0] = __ldg(reinterpret_cast<const uint4*>(g_W_lo + g0));
            Bl[1] = __ldg(reinterpret_cast<const uint4*>(g_W_lo + g1));
        }

        // ---- mma phase ----
        static __shared__ float dummy;  (void)dummy;
        {
            // accumulators live across kc within an ac chunk
            // (declared outside loop via persistent storage below)
        }
        // NOTE: accumulators are declared below; see acc[]
        // (handled by splitting loop manually)
        // -- actual mma work happens here via the acc array defined before the loop --
        {
            extern __shared__ char smem2[];   // same smem
            (void)smem2;
        }
        // mma body inlined:
        {
            // see acc definition before loop
        }
        // real body:
        goto mma_body;
    mma_body_done:
        // epilogue at end of each ac chunk
        if ((it & 7) == 7) {
            goto epilogue_body;
        }
    epilogue_done:
        continue;

    mma_body: {
        static_assert(true, "");
        goto mma_real;
    }
    mma_real: {
        // placeholder to satisfy structure; actual code below replaces this flow
        goto mma_body_done;
    }
    epilogue_body: {
        goto epilogue_done;
    }
    }

    // unreachable layout guard (real implementation follows in score_mma_kernel2)
    if (tid == -1) out[0] = 0.f;
}

// The goto-structured version above is fragile; provide the clean implementation
// actually used:
extern "C" __global__ void __launch_bounds__(NTHR, 1)
score_mma2_kernel(const float* __restrict__ enc,
                  const float* __restrict__ v_a,
                  float* __restrict__ out) {
    extern __shared__ char smem[];
    const uint32_t sb = smem_u32(smem);
    const int tid = threadIdx.x;
    const int lane = tid & 31, wid = tid >> 5;
    const int g = lane >> 2, c = lane & 3, l7 = lane & 7;
    const int t8 = (lane >> 3) & 1, t16 = lane >> 4;
    const int wm = wid & 3, wn = wid >> 2;
    const int mbase = wm * 32, nbase = wn * 32;
    const int b = blockIdx.y, s0 = blockIdx.x * MT;

    float* dec_s = reinterpret_cast<float*>(smem + SM_DEC);
    float* v_s   = reinterpret_cast<float*>(smem + SM_V);
    float* score = reinterpret_cast<float*>(smem + SM_SCORE);
    if (tid < 512) {
        dec_s[tid] = g_dec_att[b * ATT + tid];
        v_s[tid]   = __ldg(v_a + tid);
    }
    if (tid < MT) score[tid] = 0.f;

    const int arow = mbase + t8 * 8 + l7;
    const int brow = nbase + t16 * 8 + l7;
    const int axor = arow & 7;
    const int bxor = brow & 7;
    const uint32_t uAh = sb + SM_A_HI, uAl = sb + SM_A_LO;
    const uint32_t uBh = sb + SM_B_HI, uBl = sb + SM_B_LO;

    float4 Araw[4];
    uint4  Bh[2], Bl[2];
    const int q0 = tid, q1 = tid + NTHR;
    const int ar0 = q0 >> 3, ak0 = q0 & 7;
    const int ar1 = q1 >> 3, ak1 = q1 & 7;
    const uint32_t sw0 = (uint32_t)(ar0 * 128 + ((ak0 ^ (ar0 & 7)) << 4));
    const uint32_t sw1 = (uint32_t)(ar1 * 128 + ((ak1 ^ (ar1 & 7)) << 4));

    // prologue stage (ac=0, kc=0)
    {
        const float4* p0 = reinterpret_cast<const float4*>(
            enc + ((size_t)(s0 + ar0) * BATCH + b) * HID + ak0 * 8);
        const float4* p1 = reinterpret_cast<const float4*>(
            enc + ((size_t)(s0 + ar1) * BATCH + b) * HID + ak1 * 8);
        Araw[0] = __ldg(p0); Araw[1] = __ldg(p0 + 1);
        Araw[2] = __ldg(p1); Araw[3] = __ldg(p1 + 1);
        size_t g0 = (size_t)ar0 * HID + ak0 * 8;
        size_t g1 = (size_t)ar1 * HID + ak1 * 8;
        Bh[0] = __ldg(reinterpret_cast<const uint4*>(g_W_hi + g0));
        Bh[1] = __ldg(reinterpret_cast<const uint4*>(g_W_hi + g1));
        Bl[0] = __ldg(reinterpret_cast<const uint4*>(g_W_lo + g0));
        Bl[1] = __ldg(reinterpret_cast<const uint4*>(g_W_lo + g1));
    }

    float acc[2][4][4];

    for (int ac = 0; ac < 4; ++ac) {
#pragma unroll
        for (int mi = 0; mi < 2; ++mi)
#pragma unroll
            for (int nj = 0; nj < 4; ++nj)
#pragma unroll
                for (int e = 0; e < 4; ++e) acc[mi][nj][e] = 0.f;

        for (int kc = 0; kc < 8; ++kc) {
            __syncthreads();
            // STS phase
            {
                uint4 h, l;
                h.x = split2(Araw[0].x, Araw[0].y, l.x);
                h.y = split2(Araw[0].z, Araw[0].w, l.y);
                h.z = split2(Araw[1].x, Araw[1].y, l.z);
                h.w = split2(Araw[1].z, Araw[1].w, l.w);
                *reinterpret_cast<uint4*>(smem + SM_A_HI + sw0) = h;
                *reinterpret_cast<uint4*>(smem + SM_A_LO + sw0) = l;
                h.x = split2(Araw[2].x, Araw[2].y, l.x);
                h.y = split2(Araw[2].z, Araw[2].w, l.y);
                h.z = split2(Araw[3].x, Araw[3].y, l.z);
                h.w = split2(Araw[3].z, Araw[3].w, l.w);
                *reinterpret_cast<uint4*>(smem + SM_A_HI + sw1) = h;
                *reinterpret_cast<uint4*>(smem + SM_A_LO + sw1) = l;
                *reinterpret_cast<uint4*>(smem + SM_B_HI + sw0) = Bh[0];
                *reinterpret_cast<uint4*>(smem + SM_B_HI + sw1) = Bh[1];
                *reinterpret_cast<uint4*>(smem + SM_B_LO + sw0) = Bl[0];
                *reinterpret_cast<uint4*>(smem + SM_B_LO + sw1) = Bl[1];
            }
            __syncthreads();

            // stage next chunk
            const int it = ac * 8 + kc;
            if (it + 1 < 32) {
                const int nac = (it + 1) >> 3, nkc = (it + 1) & 7;
                const int k0 = nkc * KC, a0 = nac * AC_N;
                const float4* p0 = reinterpret_cast<const float4*>(
                    enc + ((size_t)(s0 + ar0) * BATCH + b) * HID + k0 + ak0 * 8);
                const float4* p1 = reinterpret_cast<const float4*>(
                    enc + ((size_t)(s0 + ar1) * BATCH + b) * HID + k0 + ak1 * 8);
                Araw[0] = __ldg(p0); Araw[1] = __ldg(p0 + 1);
                Araw[2] = __ldg(p1); Araw[3] = __ldg(p1 + 1);
                size_t g0 = (size_t)(a0 + ar0) * HID + k0 + ak0 * 8;
                size_t g1 = (size_t)(a0 + ar1) * HID + k0 + ak1 * 8;
                Bh[0] = __ldg(reinterpret_cast<const uint4*>(g_W_hi + g0));
                Bh[1] = __ldg(reinterpret_cast<const uint4*>(g_W_hi + g1));
                Bl[0] = __ldg(reinterpret_cast<const uint4*>(g_W_lo + g0));
                Bl[1] = __ldg(reinterpret_cast<const uint4*>(g_W_lo + g1));
            }

            // mma phase: 4 k16 steps
#pragma unroll
            for (int ks = 0; ks < 4; ++ks) {
                const int acnk = 2 * ks + t16;   // A chunk idx
                const int bcnk = 2 * ks + t8;    // B chunk idx
                uint32_t ah0[4], ah1[4], b0[4], b1[4], t[4];

                ldsm4(uAh + arow * 128 + ((acnk ^ axor) << 4), ah0);
                ldsm4(uAh + (arow + 16) * 128 + ((acnk ^ axor) << 4), ah1);
                ldsm4(uBh + brow * 128 + ((bcnk ^ bxor) << 4), b0);
                ldsm4(uBh + (brow + 16) * 128 + ((bcnk ^ bxor) << 4), b1);

                MMA(acc[0][0], ah0, b0[0], b0[1]);
                MMA(acc[0][1], ah0, b0[2], b0[3]);
                MMA(acc[0][2], ah0, b1[0], b1[1]);
                MMA(acc[0][3], ah0, b1[2], b1[3]);
                MMA(acc[1][0], ah1, b0[0], b0[1]);
                MMA(acc[1][1], ah1, b0[2], b0[3]);
                MMA(acc[1][2], ah1, b1[0], b1[1]);
                MMA(acc[1][3], ah1, b1[2], b1[3]);

                // e_lo * w_hi (reuse b0/b1)
                ldsm4(uAl + arow * 128 + ((acnk ^ axor) << 4), t);
                MMA(acc[0][0], t, b0[0], b0[1]);
                MMA(acc[0][1], t, b0[2], b0[3]);
                MMA(acc[0][2], t, b1[0], b1[1]);
                MMA(acc[0][3], t, b1[2], b1[3]);
                ldsm4(uAl + (arow + 16) * 128 + ((acnk ^ axor) << 4), t);
                MMA(acc[1][0], t, b0[0], b0[1]);
                MMA(acc[1][1], t, b0[2], b0[3]);
                MMA(acc[1][2], t, b1[0], b1[1]);
                MMA(acc[1][3], t, b1[2], b1[3]);

                // e_hi * w_lo (reuse ah0/ah1)
                ldsm4(uBl + brow * 128 + ((bcnk ^ bxor) << 4), b0);
                ldsm4(uBl + (brow + 16) * 128 + ((bcnk ^ bxor) << 4), b1);
                MMA(acc[0][0], ah0, b0[0], b0[1]);
                MMA(acc[0][1], ah0, b0[2], b0[3]);
                MMA(acc[0][2], ah0, b1[0], b1[1]);
                MMA(acc[0][3], ah0, b1[2], b1[3]);
                MMA(acc[1][0], ah1, b0[0], b0[1]);
                MMA(acc[1][1], ah1, b0[2], b0[3]);
                MMA(acc[1][2], ah1, b1[0], b1[1]);
                MMA(acc[1][3], ah1, b1[2], b1[3]);
            }
        }

        // epilogue for this a-chunk: tanh + v reduction
        {
            const int a0 = ac * AC_N;
            float pm[4] = {0.f, 0.f, 0.f, 0.f};
#pragma unroll
            for (int mi = 0; mi < 2; ++mi)
#pragma unroll
                for (int nj = 0; nj < 4; ++nj) {
                    const int n = a0 + nbase + nj * 8 + 2 * c;
                    const float d0 = dec_s[n - a0 + a0];   // dec_s indexed by global a
                    const float dn0 = dec_s[n], dn1 = dec_s[n + 1];
                    const float vn0 = v_s[n],  vn1 = v_s[n + 1];
                    pm[mi * 2 + 0] += vn0 * tanh_fast(acc[mi][nj][0] + dn0)
                                    + vn1 * tanh_fast(acc[mi][nj][1] + dn1);
                    pm[mi * 2 + 1] += vn0 * tanh_fast(acc[mi][nj][2] + dn0)
                                    + vn1 * tanh_fast(acc[mi][nj][3] + dn1);
                    (void)d0;
                }
            atomicAdd(&score[mbase +  0 + g], pm[0]);
            atomicAdd(&score[mbase +  8 + g], pm[1]);
            atomicAdd(&score[mbase + 16 + g], pm[2]);
            atomicAdd(&score[mbase + 24 + g], pm[3]);
        }
    }

    __syncthreads();
    if (tid < MT) out[(size_t)b * S_LEN + s0 + tid] = score[tid];
}

// ---------------- launch ----------------
extern "C" void kernel_launch(void* const* d_in, const int* in_sizes, int n_in,
                              void* d_out, int out_size) {
    const float* dec_out = (const float*)d_in[0];
    const float* enc     = (const float*)d_in[1];
    const float* W_s     = (const float*)d_in[2];
    const float* W_t     = (const float*)d_in[3];
    const float* b_t     = (const float*)d_in[4];
    const float* v_a     = (const float*)d_in[5];
    float* out = (float*)d_out;
    (void)in_sizes; (void)n_in; (void)out_size;

    cudaFuncSetAttribute(score_mma2_kernel,
                         cudaFuncAttributeMaxDynamicSharedMemorySize, SM_TOTAL);

    w_prep_kernel<<<ATT * HID / 512, 512>>>(W_s);
    dec_att_kernel<<<BATCH, 256>>>(dec_out, W_t, b_t);

    dim3 grid(S_LEN / MT, BATCH);   // (16, 64)
    score_mma2_kernel<<<grid, NTHR, SM_TOTAL>>>(enc, v_a, out);
}